// round 16
// baseline (speedup 1.0000x reference)
#include <cuda_runtime.h>
#include <cuda_fp16.h>
#include <cstdint>

// Complex attention via portable mma.sync m16n8k16 fp16 (f32 accum).
// Round 16: R13 structure (full-batch QK, register-resident P, 2 CTAs/SM)
// + exp moved off the MUFU pipe: exp(m) = 2^(m*log2e) via magic-number
// range reduction + degree-5 polynomial on the FMA pipe. MUFU/tile halved.
#define SLEN 2048
#define PLANE (4*8*2048*64)
#define TEMP_INV 0.125f
#define NT 32
#define SGNH 0x80008000u

// smem uint4 units: K[2][1024] @0, V[2][1024] @2048
#define SMEM_BYTES (4096*16)   // 65536

__device__ uint4 gK[32*32*1024];
__device__ uint4 gV[32*32*1024];

static __device__ __forceinline__ void mma16(float* d, const uint32_t* a,
                                             uint32_t b0, uint32_t b1) {
    asm volatile("mma.sync.aligned.m16n8k16.row.col.f32.f16.f16.f32 "
                 "{%0,%1,%2,%3},{%4,%5,%6,%7},{%8,%9},{%0,%1,%2,%3};"
                 : "+f"(d[0]), "+f"(d[1]), "+f"(d[2]), "+f"(d[3])
                 : "r"(a[0]), "r"(a[1]), "r"(a[2]), "r"(a[3]), "r"(b0), "r"(b1));
}
static __device__ __forceinline__ uint32_t h2u(float x, float y) {
    __half2 h = __floats2half2_rn(x, y);
    return *(uint32_t*)&h;
}
static __device__ __forceinline__ void cp16(void* dst, const uint4* src) {
    unsigned a = (unsigned)__cvta_generic_to_shared(dst);
    asm volatile("cp.async.cg.shared.global [%0], [%1], 16;" :: "r"(a), "l"(src));
}
// exp(m) for m >= 0 (m <= ~20), FMA-pipe only. 2^z with z = m*log2e.
static __device__ __forceinline__ float fexp_pos(float m) {
    const float L2E = 1.4426950408889634f;
    const float MAGIC = 12582912.0f;            // 1.5 * 2^23
    float z  = m * L2E;
    float zj = __fadd_rn(z, MAGIC);             // j in low mantissa bits
    float jf = __fsub_rn(zj, MAGIC);            // (float)round(z)
    float f  = __fsub_rn(z, jf);                // f in [-0.5, 0.5]
    int ebits = __float_as_int(zj) << 23;       // == j << 23 (j >= 0)
    float p = 1.3298820e-3f;
    p = fmaf(p, f, 9.6181291e-3f);
    p = fmaf(p, f, 5.5504109e-2f);
    p = fmaf(p, f, 2.4022651e-1f);
    p = fmaf(p, f, 6.9314718e-1f);
    p = fmaf(p, f, 1.0f);                       // 2^f
    return __int_as_float(__float_as_int(p) + ebits);
}

// x bits: lane[0:5) ktp[5:7) nt[7:10) t[10:15) h[15:20)
__global__ __launch_bounds__(256)
void prep_k(const float* __restrict__ kr, const float* __restrict__ ki) {
    int x = blockIdx.x * 256 + threadIdx.x;
    int lane = x & 31, ktp = (x >> 5) & 3, nt = (x >> 7) & 7;
    int t = (x >> 10) & 31, h = x >> 15;
    int g = lane >> 2, l = lane & 3;
    int row = ((h << 11) + (t << 6) + (nt << 3) + g) << 6;   // *64
    int k0 = (ktp << 4) + 2 * l, k1 = k0 + 8;
    gK[x] = make_uint4(h2u(kr[row + k0], kr[row + k0 + 1]),
                       h2u(kr[row + k1], kr[row + k1 + 1]),
                       h2u(ki[row + k0], ki[row + k0 + 1]),
                       h2u(ki[row + k1], ki[row + k1 + 1]));
}
__global__ __launch_bounds__(256)
void prep_v(const float* __restrict__ vr, const float* __restrict__ vi) {
    int x = blockIdx.x * 256 + threadIdx.x;
    int lane = x & 31, ktp = (x >> 5) & 3, nt = (x >> 7) & 7;
    int t = (x >> 10) & 31, h = x >> 15;
    int g = lane >> 2, l = lane & 3;
    int d = (nt << 3) + g;
    size_t base = ((size_t)h << 17) + d;                     // h*2048*64 + d
    int key0 = ((t << 6) + (ktp << 4) + 2 * l) << 6;         // *64
    int key8 = key0 + (8 << 6);
    gV[x] = make_uint4(h2u(vr[base + key0], vr[base + key0 + 64]),
                       h2u(vr[base + key8], vr[base + key8 + 64]),
                       h2u(vi[base + key0], vi[base + key0 + 64]),
                       h2u(vi[base + key8], vi[base + key8 + 64]));
}

__global__ __launch_bounds__(128, 2)
void cvattn_mma(const float* __restrict__ qr_g, const float* __restrict__ qi_g,
                float* __restrict__ out)
{
    extern __shared__ uint4 smem4[];
    const int tid  = threadIdx.x;
    const int w    = tid >> 5;                 // 0..3
    const int lane = tid & 31;
    const int g    = lane >> 2;
    const int l    = lane & 3;
    const int bh   = blockIdx.y;
    const size_t hoff = (size_t)bh * (SLEN * 64);
    const int m0 = blockIdx.x << 6;            // 64-row query tile

    const uint4* srcK = gK + ((size_t)bh << 15);   // 32 tiles x 1024
    const uint4* srcV = gV + ((size_t)bh << 15);

    // ---- Q fragments in fp16 (rows m0+w*16+g, +8), scaled ----
    uint32_t qa[4][4], qb[4][4];
    {
        const float* Q0r = qr_g + hoff + (size_t)(m0 + w * 16 + g) * 64;
        const float* Q1r = Q0r + 8 * 64;
        const float* Q0i = qi_g + hoff + (size_t)(m0 + w * 16 + g) * 64;
        const float* Q1i = Q0i + 8 * 64;
#pragma unroll
        for (int ktp = 0; ktp < 4; ++ktp) {
            int k0 = ktp * 16 + 2 * l, k1 = k0 + 8;
            qa[ktp][0] = h2u(Q0r[k0] * TEMP_INV, Q0r[k0 + 1] * TEMP_INV);
            qa[ktp][1] = h2u(Q1r[k0] * TEMP_INV, Q1r[k0 + 1] * TEMP_INV);
            qa[ktp][2] = h2u(Q0r[k1] * TEMP_INV, Q0r[k1 + 1] * TEMP_INV);
            qa[ktp][3] = h2u(Q1r[k1] * TEMP_INV, Q1r[k1 + 1] * TEMP_INV);
            qb[ktp][0] = h2u(Q0i[k0] * TEMP_INV, Q0i[k0 + 1] * TEMP_INV);
            qb[ktp][1] = h2u(Q1i[k0] * TEMP_INV, Q1i[k0 + 1] * TEMP_INV);
            qb[ktp][2] = h2u(Q0i[k1] * TEMP_INV, Q0i[k1 + 1] * TEMP_INV);
            qb[ktp][3] = h2u(Q1i[k1] * TEMP_INV, Q1i[k1 + 1] * TEMP_INV);
        }
    }

    float ore[8][4], oim[8][4];
#pragma unroll
    for (int nt = 0; nt < 8; ++nt)
#pragma unroll
        for (int j = 0; j < 4; ++j) { ore[nt][j] = 0.f; oim[nt][j] = 0.f; }
    float lsum0 = 0.f, lsum1 = 0.f;

    // tile 0 load: K 1024 + V 1024 chunks with 128 threads
#pragma unroll
    for (int j = 0; j < 8; ++j) {
        cp16(smem4 + tid + (j << 7),        srcK + tid + (j << 7));
        cp16(smem4 + 2048 + tid + (j << 7), srcV + tid + (j << 7));
    }
    asm volatile("cp.async.commit_group;" ::: "memory");
    asm volatile("cp.async.wait_group 0;" ::: "memory");
    __syncthreads();

    for (int t = 0; t < NT; ++t) {
        if (t + 1 < NT) {
            const int nb = (t + 1) & 1, tb = (t + 1) << 10;
#pragma unroll
            for (int j = 0; j < 8; ++j) {
                cp16(smem4 + (nb << 10) + tid + (j << 7),        srcK + tb + tid + (j << 7));
                cp16(smem4 + 2048 + (nb << 10) + tid + (j << 7), srcV + tb + tid + (j << 7));
            }
        }
        asm volatile("cp.async.commit_group;" ::: "memory");

        const uint4* kb = smem4 + ((t & 1) << 10);

        // ---- S = (Q/T) K^T (complex) ----
        float sre[8][4], sim_[8][4];
#pragma unroll
        for (int nt = 0; nt < 8; ++nt)
#pragma unroll
            for (int j = 0; j < 4; ++j) { sre[nt][j] = 0.f; sim_[nt][j] = 0.f; }

#pragma unroll
        for (int ktp = 0; ktp < 4; ++ktp) {
#pragma unroll
            for (int nt = 0; nt < 8; ++nt) {
                uint4 f = kb[(((nt << 2) + ktp) << 5) + lane];
                mma16(sre[nt],  qa[ktp], f.x, f.y);
                mma16(sim_[nt], qa[ktp], f.z, f.w);
                mma16(sre[nt],  qb[ktp], f.z ^ SGNH, f.w ^ SGNH);
                mma16(sim_[nt], qb[ktp], f.x, f.y);
            }
        }

        // ---- softmax on |S| (exp on FMA pipe); P packed to fp16 in regs ----
        uint32_t prh[8][2], pih[8][2];
#pragma unroll
        for (int nt = 0; nt < 8; ++nt) {
            float pr[4], pi[4];
#pragma unroll
            for (int j = 0; j < 4; ++j) {
                float x = sre[nt][j], y = sim_[nt][j];
                float r2 = fmaf(x, x, y * y);
                float ri = rsqrtf(fmaxf(r2, 1e-24f));
                float e  = fexp_pos(r2 * ri);         // exp(|z|)
                float wt = e * ri;
                pr[j] = x * wt;
                pi[j] = y * wt;
                if (j < 2) lsum0 += e; else lsum1 += e;
            }
            prh[nt][0] = h2u(pr[0], pr[1]);
            prh[nt][1] = h2u(pr[2], pr[3]);
            pih[nt][0] = h2u(pi[0], pi[1]);
            pih[nt][1] = h2u(pi[2], pi[3]);
        }

        // ---- O += P V (complex), A-frags straight from registers ----
        const uint4* vb = smem4 + 2048 + ((t & 1) << 10);
#pragma unroll
        for (int ktp = 0; ktp < 4; ++ktp) {
            uint32_t ap[4]  = {prh[2*ktp][0], prh[2*ktp][1], prh[2*ktp+1][0], prh[2*ktp+1][1]};
            uint32_t ai[4]  = {pih[2*ktp][0], pih[2*ktp][1], pih[2*ktp+1][0], pih[2*ktp+1][1]};
            uint32_t ain[4] = {ai[0] ^ SGNH, ai[1] ^ SGNH, ai[2] ^ SGNH, ai[3] ^ SGNH};
#pragma unroll
            for (int nt = 0; nt < 8; ++nt) {
                uint4 v = vb[(((nt << 2) + ktp) << 5) + lane];
                mma16(ore[nt], ap,  v.x, v.y);
                mma16(oim[nt], ap,  v.z, v.w);
                mma16(ore[nt], ain, v.z, v.w);
                mma16(oim[nt], ai,  v.x, v.y);
            }
        }

        asm volatile("cp.async.wait_group 0;" ::: "memory");
        __syncthreads();
    }

    // ---- epilogue ----
    lsum0 += __shfl_xor_sync(0xffffffffu, lsum0, 1);
    lsum0 += __shfl_xor_sync(0xffffffffu, lsum0, 2);
    lsum1 += __shfl_xor_sync(0xffffffffu, lsum1, 1);
    lsum1 += __shfl_xor_sync(0xffffffffu, lsum1, 2);
    const float inv0 = 1.0f / lsum0;
    const float inv1 = 1.0f / lsum1;

    float* OutR = out + hoff;
    float* OutI = out + (size_t)PLANE + hoff;
    const int r0 = (m0 + w * 16 + g) * 64;
    const int r1 = r0 + 8 * 64;
#pragma unroll
    for (int nt = 0; nt < 8; ++nt) {
        int c = nt * 8 + 2 * l;
        *(float2*)(OutR + r0 + c) = make_float2(ore[nt][0] * inv0, ore[nt][1] * inv0);
        *(float2*)(OutI + r0 + c) = make_float2(oim[nt][0] * inv0, oim[nt][1] * inv0);
        *(float2*)(OutR + r1 + c) = make_float2(ore[nt][2] * inv1, ore[nt][3] * inv1);
        *(float2*)(OutI + r1 + c) = make_float2(oim[nt][2] * inv1, oim[nt][3] * inv1);
    }
}

extern "C" void kernel_launch(void* const* d_in, const int* in_sizes, int n_in,
                              void* d_out, int out_size)
{
    (void)in_sizes; (void)n_in; (void)out_size;
    prep_k<<<4096, 256>>>((const float*)d_in[2], (const float*)d_in[3]);
    prep_v<<<4096, 256>>>((const float*)d_in[4], (const float*)d_in[5]);

    cudaFuncSetAttribute(cvattn_mma, cudaFuncAttributeMaxDynamicSharedMemorySize, SMEM_BYTES);
    dim3 grid(SLEN / 64, 32);
    cvattn_mma<<<grid, 128, SMEM_BYTES>>>(
        (const float*)d_in[0], (const float*)d_in[1], (float*)d_out);
}